// round 3
// baseline (speedup 1.0000x reference)
#include <cuda_runtime.h>
#include <math.h>

// Problem constants
#define B_    2
#define N_    8192
#define C_    2048
#define H_    16
#define HD_   128
#define GS_   256
#define G_    (N_/GS_)     // 32
#define HALF_ 8
#define SHIFT_ 128
#define SCALE_ 0.08838834764831843f   // 1/sqrt(128)

// scratch: qkv[3][B][H][N][HD]  (shift already applied at write time)
__device__ float g_qkv[(size_t)3 * B_ * H_ * N_ * HD_];

// ---------------------------------------------------------------------------
// Projection GEMM: out[m, c] = sum_k x[m,k] * W[c,k] + bias[c]
// Tile 128x128x16, 256 threads, 8x8 microtile, double-buffered smem.
// Epilogue scatters into g_qkv with head split + sequence shift.
// ---------------------------------------------------------------------------
#define BM 128
#define BN 128
#define BK 16

__global__ __launch_bounds__(256) void proj_kernel(
    const float* __restrict__ x,
    const float* __restrict__ Wq, const float* __restrict__ bq,
    const float* __restrict__ Wk, const float* __restrict__ bk,
    const float* __restrict__ Wv, const float* __restrict__ bv)
{
    const int z = blockIdx.z;                       // 0=q,1=k,2=v
    const float* __restrict__ W    = (z == 0) ? Wq : (z == 1) ? Wk : Wv;
    const float* __restrict__ bias = (z == 0) ? bq : (z == 1) ? bk : bv;

    const int m0 = blockIdx.x * BM;
    const int h  = blockIdx.y;                      // BN==HD -> one head per tile
    const int n0 = h * BN;

    __shared__ float As[2][BK][BM];
    __shared__ float Bs[2][BK][BN];

    const int tid = threadIdx.x;
    const int tx = tid & 15;
    const int ty = tid >> 4;

    float4 a_reg[2], b_reg[2];

    auto ldg = [&](int kb) {
        const int k0 = kb * BK;
        #pragma unroll
        for (int i = 0; i < 2; i++) {
            int f  = tid + 256 * i;      // 0..511  (512 float4 per tile)
            int m  = f >> 2;             // 0..127
            int k4 = f & 3;              // 0..3
            a_reg[i] = *(const float4*)(x + (size_t)(m0 + m) * C_ + k0 + k4 * 4);
            b_reg[i] = *(const float4*)(W + (size_t)(n0 + m) * C_ + k0 + k4 * 4);
        }
    };
    auto sts = [&](int buf) {
        #pragma unroll
        for (int i = 0; i < 2; i++) {
            int f  = tid + 256 * i;
            int m  = f >> 2;
            int k4 = f & 3;
            As[buf][k4*4+0][m] = a_reg[i].x;
            As[buf][k4*4+1][m] = a_reg[i].y;
            As[buf][k4*4+2][m] = a_reg[i].z;
            As[buf][k4*4+3][m] = a_reg[i].w;
            Bs[buf][k4*4+0][m] = b_reg[i].x;
            Bs[buf][k4*4+1][m] = b_reg[i].y;
            Bs[buf][k4*4+2][m] = b_reg[i].z;
            Bs[buf][k4*4+3][m] = b_reg[i].w;
        }
    };

    float acc[8][8];
    #pragma unroll
    for (int i = 0; i < 8; i++)
        #pragma unroll
        for (int j = 0; j < 8; j++) acc[i][j] = 0.f;

    const int nk = C_ / BK;   // 128
    ldg(0); sts(0); __syncthreads();

    for (int kb = 0; kb < nk; kb++) {
        const int cur = kb & 1;
        if (kb + 1 < nk) ldg(kb + 1);
        #pragma unroll
        for (int kk = 0; kk < BK; kk++) {
            float4 a0 = *(const float4*)&As[cur][kk][ty * 4];
            float4 a1 = *(const float4*)&As[cur][kk][64 + ty * 4];
            float4 b0 = *(const float4*)&Bs[cur][kk][tx * 4];
            float4 b1 = *(const float4*)&Bs[cur][kk][64 + tx * 4];
            float ra[8] = {a0.x, a0.y, a0.z, a0.w, a1.x, a1.y, a1.z, a1.w};
            float rb[8] = {b0.x, b0.y, b0.z, b0.w, b1.x, b1.y, b1.z, b1.w};
            #pragma unroll
            for (int i = 0; i < 8; i++)
                #pragma unroll
                for (int j = 0; j < 8; j++)
                    acc[i][j] = fmaf(ra[i], rb[j], acc[i][j]);
        }
        if (kb + 1 < nk) sts((kb + 1) & 1);
        __syncthreads();
    }

    // bias for this thread's 8 columns
    float bb[8];
    #pragma unroll
    for (int j = 0; j < 4; j++) {
        bb[j]     = bias[(size_t)h * HD_ + tx * 4 + j];
        bb[4 + j] = bias[(size_t)h * HD_ + 64 + tx * 4 + j];
    }

    float* outb = g_qkv + (size_t)z * B_ * H_ * N_ * HD_;
    #pragma unroll
    for (int ii = 0; ii < 8; ii++) {
        const int r    = (ii < 4) ? (ty * 4 + ii) : (64 + ty * 4 + (ii - 4));
        const int mg   = m0 + r;
        const int b    = mg >> 13;               // /8192
        const int nsrc = mg & (N_ - 1);
        // shifted[n] = orig[(n+128)%N] for h>=8  -> source nsrc lands at nsrc-128
        const int ndst = (h < HALF_) ? nsrc : ((nsrc - SHIFT_) & (N_ - 1));
        float* orow = outb + (((size_t)b * H_ + h) * N_ + ndst) * HD_;
        float4 o0 = make_float4(acc[ii][0] + bb[0], acc[ii][1] + bb[1],
                                acc[ii][2] + bb[2], acc[ii][3] + bb[3]);
        float4 o1 = make_float4(acc[ii][4] + bb[4], acc[ii][5] + bb[5],
                                acc[ii][6] + bb[6], acc[ii][7] + bb[7]);
        *(float4*)(orow + tx * 4)      = o0;
        *(float4*)(orow + 64 + tx * 4) = o1;
    }
}

// ---------------------------------------------------------------------------
// Attention: one CTA per (b, h, group, q-tile of 64 rows). 256 threads.
// Phase A: S = Q Kt / sqrt(hd) with causal mask, into smem (64 x 256)
// Phase B: row softmax in smem
// Phase C: O = P V, write to output with unshift + head interleave
// ---------------------------------------------------------------------------
#define QT_ 64
#define NQT 4            // q-tiles per group (GS_/QT_)
#define TSTR 68          // padded stride for transposed Q/K tiles [d][q]
#define SSTR 260         // padded stride for score rows

__global__ __launch_bounds__(256) void attn_kernel(float* __restrict__ y)
{
    extern __shared__ float sm[];
    float* Qt  = sm;                         // [128][TSTR]  transposed Q tile
    float* KVt = sm + 128 * TSTR;            // K: [128][TSTR] / V: [64][128]
    float* Ss  = sm + 2 * 128 * TSTR;        // [64][SSTR]

    const int tid = threadIdx.x;
    const int tx = tid & 15;
    const int ty = tid >> 4;

    const int qt = blockIdx.x;               // 0..3
    const int g  = blockIdx.y;               // 0..31
    const int bh = blockIdx.z;               // 0..31
    const int b  = bh >> 4;
    const int h  = bh & 15;

    const size_t plane = ((size_t)b * H_ + h) * (size_t)N_ * HD_;
    const size_t PSZ   = (size_t)B_ * H_ * N_ * HD_;
    const float* qp = g_qkv + plane + (size_t)(g * GS_ + qt * QT_) * HD_;
    const float* kp = g_qkv + PSZ     + plane + (size_t)(g * GS_) * HD_;
    const float* vp = g_qkv + 2 * PSZ + plane + (size_t)(g * GS_) * HD_;

    // load Q tile transposed: Qt[d][r]
    #pragma unroll
    for (int i = 0; i < 8; i++) {
        int f  = tid + 256 * i;    // 0..2047 (64 rows x 32 float4)
        int r  = f >> 5;
        int d4 = f & 31;
        float4 v = *(const float4*)(qp + (size_t)r * HD_ + d4 * 4);
        Qt[(d4 * 4 + 0) * TSTR + r] = v.x;
        Qt[(d4 * 4 + 1) * TSTR + r] = v.y;
        Qt[(d4 * 4 + 2) * TSTR + r] = v.z;
        Qt[(d4 * 4 + 3) * TSTR + r] = v.w;
    }

    // -------- Phase A: scores --------
    for (int kt = 0; kt <= qt; kt++) {
        __syncthreads();
        #pragma unroll
        for (int i = 0; i < 8; i++) {
            int f  = tid + 256 * i;
            int r  = f >> 5;
            int d4 = f & 31;
            float4 v = *(const float4*)(kp + ((size_t)kt * QT_ + r) * HD_ + d4 * 4);
            KVt[(d4 * 4 + 0) * TSTR + r] = v.x;
            KVt[(d4 * 4 + 1) * TSTR + r] = v.y;
            KVt[(d4 * 4 + 2) * TSTR + r] = v.z;
            KVt[(d4 * 4 + 3) * TSTR + r] = v.w;
        }
        __syncthreads();

        float s[4][4];
        #pragma unroll
        for (int i = 0; i < 4; i++)
            #pragma unroll
            for (int j = 0; j < 4; j++) s[i][j] = 0.f;

        #pragma unroll 4
        for (int d = 0; d < HD_; d++) {
            float4 qf = *(const float4*)&Qt[d * TSTR + ty * 4];
            float4 kf = *(const float4*)&KVt[d * TSTR + tx * 4];
            float rq[4] = {qf.x, qf.y, qf.z, qf.w};
            float rk[4] = {kf.x, kf.y, kf.z, kf.w};
            #pragma unroll
            for (int i = 0; i < 4; i++)
                #pragma unroll
                for (int j = 0; j < 4; j++)
                    s[i][j] = fmaf(rq[i], rk[j], s[i][j]);
        }
        #pragma unroll
        for (int i = 0; i < 4; i++) {
            int qi = qt * QT_ + ty * 4 + i;
            #pragma unroll
            for (int j = 0; j < 4; j++) {
                int ki = kt * QT_ + tx * 4 + j;
                Ss[(ty * 4 + i) * SSTR + ki] = (ki > qi) ? -1e9f : s[i][j] * SCALE_;
            }
        }
    }
    __syncthreads();

    // -------- Phase B: softmax (8 warps x 8 rows) --------
    {
        const int L = (qt + 1) * QT_;
        const int warp = tid >> 5, lane = tid & 31;
        for (int rr = 0; rr < 8; rr++) {
            float* row = Ss + (warp * 8 + rr) * SSTR;
            float m = -1e30f;
            for (int j = lane; j < L; j += 32) m = fmaxf(m, row[j]);
            #pragma unroll
            for (int o = 16; o; o >>= 1) m = fmaxf(m, __shfl_xor_sync(~0u, m, o));
            float sum = 0.f;
            for (int j = lane; j < L; j += 32) { float e = expf(row[j] - m); row[j] = e; sum += e; }
            #pragma unroll
            for (int o = 16; o; o >>= 1) sum += __shfl_xor_sync(~0u, sum, o);
            float inv = 1.f / sum;
            for (int j = lane; j < L; j += 32) row[j] *= inv;
        }
    }

    // -------- Phase C: O = P V --------
    float acc[4][8];
    #pragma unroll
    for (int i = 0; i < 4; i++)
        #pragma unroll
        for (int j = 0; j < 8; j++) acc[i][j] = 0.f;

    for (int kt = 0; kt <= qt; kt++) {
        __syncthreads();   // Ss/softmax done (first iter) / prev V reads done
        #pragma unroll
        for (int i = 0; i < 8; i++) {
            int f  = tid + 256 * i;
            int r  = f >> 5;
            int d4 = f & 31;
            *(float4*)&KVt[r * 128 + d4 * 4] =
                *(const float4*)(vp + ((size_t)kt * QT_ + r) * HD_ + d4 * 4);
        }
        __syncthreads();

        #pragma unroll 2
        for (int kk = 0; kk < QT_; kk++) {
            const int kcol = kt * QT_ + kk;
            float p0 = Ss[(ty * 4 + 0) * SSTR + kcol];
            float p1 = Ss[(ty * 4 + 1) * SSTR + kcol];
            float p2 = Ss[(ty * 4 + 2) * SSTR + kcol];
            float p3 = Ss[(ty * 4 + 3) * SSTR + kcol];
            float4 v0 = *(const float4*)&KVt[kk * 128 + tx * 4];
            float4 v1 = *(const float4*)&KVt[kk * 128 + 64 + tx * 4];
            float rv[8] = {v0.x, v0.y, v0.z, v0.w, v1.x, v1.y, v1.z, v1.w};
            float rp[4] = {p0, p1, p2, p3};
            #pragma unroll
            for (int i = 0; i < 4; i++)
                #pragma unroll
                for (int j = 0; j < 8; j++)
                    acc[i][j] = fmaf(rp[i], rv[j], acc[i][j]);
        }
    }

    // write out: unshift (+128 for h>=8) and interleave heads
    #pragma unroll
    for (int i = 0; i < 4; i++) {
        int np = g * GS_ + qt * QT_ + ty * 4 + i;                 // shifted position
        int nf = (h < HALF_) ? np : ((np + SHIFT_) & (N_ - 1));   // final position
        float* orow = y + ((size_t)b * N_ + nf) * C_ + (size_t)h * HD_;
        *(float4*)(orow + tx * 4) =
            make_float4(acc[i][0], acc[i][1], acc[i][2], acc[i][3]);
        *(float4*)(orow + 64 + tx * 4) =
            make_float4(acc[i][4], acc[i][5], acc[i][6], acc[i][7]);
    }
}

// ---------------------------------------------------------------------------
extern "C" void kernel_launch(void* const* d_in, const int* in_sizes, int n_in,
                              void* d_out, int out_size)
{
    const float* x  = (const float*)d_in[0];
    const float* Wq = (const float*)d_in[1];
    const float* bq = (const float*)d_in[2];
    const float* Wk = (const float*)d_in[3];
    const float* bk = (const float*)d_in[4];
    const float* Wv = (const float*)d_in[5];
    const float* bv = (const float*)d_in[6];
    float* y = (float*)d_out;

    // projections (q,k,v) with fused shift
    proj_kernel<<<dim3((B_ * N_) / BM, C_ / BN, 3), 256>>>(x, Wq, bq, Wk, bk, Wv, bv);

    // attention: 4 q-tiles per group, 32 groups, 32 (b,h) planes
    const int att_smem = (2 * 128 * TSTR + 64 * SSTR) * (int)sizeof(float); // 136192 B
    cudaFuncSetAttribute(attn_kernel,
                         cudaFuncAttributeMaxDynamicSharedMemorySize, att_smem);
    attn_kernel<<<dim3(NQT, G_, B_ * H_), 256, att_smem>>>(y);
}

// round 5
// speedup vs baseline: 2.6244x; 2.6244x over previous
#include <cuda_runtime.h>
#include <cuda_bf16.h>
#include <math.h>
#include <stdint.h>

// ---------------------------------------------------------------------------
// Problem constants
// ---------------------------------------------------------------------------
#define B_    2
#define N_    8192
#define C_    2048
#define H_    16
#define HD_   128
#define GS_   256
#define G_    (N_/GS_)     // 32
#define HALF_ 8
#define SHIFT_ 128
#define SCALE_ 0.08838834764831843f   // 1/sqrt(128)

#define MROWS (B_*N_)      // 16384
#define K6    (3*C_)       // 6144 augmented K: [hi|lo|hi] x [hi|hi|lo]

// scratch
__device__ float g_qkv[(size_t)3 * B_ * H_ * N_ * HD_];
__device__ __nv_bfloat16 g_A[(size_t)MROWS * K6];            // x_aug  [16384][6144]
__device__ __nv_bfloat16 g_B[(size_t)3 * C_ * K6];           // W_aug  [3][2048][6144]

// ---------------------------------------------------------------------------
// split: fp32 [rows][2048] -> bf16 [rows][6144]; hi at col 0 and hi2_off, lo at lo_off
// ---------------------------------------------------------------------------
__global__ __launch_bounds__(256) void split_kernel(
    const float* __restrict__ in, __nv_bfloat16* __restrict__ out,
    int hi2_off, int lo_off)
{
    size_t idx = (size_t)blockIdx.x * 256 + threadIdx.x;   // one float4 each
    float4 v = ((const float4*)in)[idx];
    size_t m  = idx >> 9;          // 512 float4 per row
    int    c  = (int)(idx & 511) * 4;

    __nv_bfloat16 h0 = __float2bfloat16(v.x);
    __nv_bfloat16 h1 = __float2bfloat16(v.y);
    __nv_bfloat16 h2 = __float2bfloat16(v.z);
    __nv_bfloat16 h3 = __float2bfloat16(v.w);
    __nv_bfloat16 l0 = __float2bfloat16(v.x - __bfloat162float(h0));
    __nv_bfloat16 l1 = __float2bfloat16(v.y - __bfloat162float(h1));
    __nv_bfloat16 l2 = __float2bfloat16(v.z - __bfloat162float(h2));
    __nv_bfloat16 l3 = __float2bfloat16(v.w - __bfloat162float(h3));

    __nv_bfloat162 hA(h0, h1), hB(h2, h3), lA(l0, l1), lB(l2, l3);
    __nv_bfloat16* rowp = out + m * K6;
    *(__nv_bfloat162*)(rowp + c)               = hA;
    *(__nv_bfloat162*)(rowp + c + 2)           = hB;
    *(__nv_bfloat162*)(rowp + hi2_off + c)     = hA;
    *(__nv_bfloat162*)(rowp + hi2_off + c + 2) = hB;
    *(__nv_bfloat162*)(rowp + lo_off + c)      = lA;
    *(__nv_bfloat162*)(rowp + lo_off + c + 2)  = lB;
}

// ---------------------------------------------------------------------------
// HMMA GEMM: D[m,n] = sum_k A[m,k]*B[n,k]  (K=6144), tile 128x128, 8 warps
// ---------------------------------------------------------------------------
#define KC   32            // k per chunk
#define LDA  40            // padded smem stride (bf16) -> 80B, conflict-free
#define NCH  (K6/KC)       // 192

__device__ __forceinline__ uint32_t s2u(const void* p) {
    uint32_t a;
    asm("{ .reg .u64 t; cvta.to.shared.u64 t, %1; cvt.u32.u64 %0, t; }"
        : "=r"(a) : "l"(p));
    return a;
}
__device__ __forceinline__ void ldmx4(uint32_t* r, uint32_t addr) {
    asm volatile("ldmatrix.sync.aligned.m8n8.x4.shared.b16 {%0,%1,%2,%3}, [%4];"
                 : "=r"(r[0]), "=r"(r[1]), "=r"(r[2]), "=r"(r[3]) : "r"(addr));
}
__device__ __forceinline__ void mma16816(float* c, const uint32_t* a,
                                         uint32_t b0, uint32_t b1) {
    asm volatile(
        "mma.sync.aligned.m16n8k16.row.col.f32.bf16.bf16.f32 "
        "{%0,%1,%2,%3}, {%4,%5,%6,%7}, {%8,%9}, {%0,%1,%2,%3};"
        : "+f"(c[0]), "+f"(c[1]), "+f"(c[2]), "+f"(c[3])
        : "r"(a[0]), "r"(a[1]), "r"(a[2]), "r"(a[3]), "r"(b0), "r"(b1));
}

__global__ __launch_bounds__(256, 2) void gemm_kernel(
    const float* __restrict__ bq, const float* __restrict__ bk,
    const float* __restrict__ bv)
{
    __shared__ __nv_bfloat16 sA[2][128][LDA];
    __shared__ __nv_bfloat16 sB[2][128][LDA];

    const int tid  = threadIdx.x;
    const int wid  = tid >> 5, lane = tid & 31;
    const int wm   = wid & 3;          // warp row (32 rows)
    const int wn   = wid >> 2;         // warp col (64 cols)

    const int n0 = blockIdx.x * 128;   // n fastest: B stays hot in L2
    const int m0 = blockIdx.y * 128;
    const int z  = blockIdx.z;
    const __nv_bfloat16* __restrict__ Ap = g_A + (size_t)m0 * K6;
    const __nv_bfloat16* __restrict__ Bp = g_B + (size_t)z * C_ * K6 + (size_t)n0 * K6;
    const float* __restrict__ bias = (z == 0) ? bq : (z == 1) ? bk : bv;

    float acc[2][8][4];
    #pragma unroll
    for (int i = 0; i < 2; i++)
        #pragma unroll
        for (int j = 0; j < 8; j++)
            #pragma unroll
            for (int k = 0; k < 4; k++) acc[i][j][k] = 0.f;

    uint4 ra[2], rb[2];
    auto ldg = [&](int c) {
        const size_t k0 = (size_t)c * KC;
        #pragma unroll
        for (int i = 0; i < 2; i++) {
            int f = tid + 256 * i, row = f >> 2, c8 = (f & 3) * 8;
            ra[i] = *(const uint4*)(Ap + (size_t)row * K6 + k0 + c8);
            rb[i] = *(const uint4*)(Bp + (size_t)row * K6 + k0 + c8);
        }
    };
    auto sts = [&](int buf) {
        #pragma unroll
        for (int i = 0; i < 2; i++) {
            int f = tid + 256 * i, row = f >> 2, c8 = (f & 3) * 8;
            *(uint4*)&sA[buf][row][c8] = ra[i];
            *(uint4*)&sB[buf][row][c8] = rb[i];
        }
    };

    const int lrow = lane & 15;        // ldmatrix row select
    const int lcol = (lane >> 4) * 8;  // ldmatrix col half

    ldg(0); sts(0); __syncthreads();

    for (int c = 0; c < NCH; c++) {
        const int buf = c & 1;
        if (c + 1 < NCH) ldg(c + 1);

        #pragma unroll
        for (int ks = 0; ks < 2; ks++) {
            const int k0 = ks * 16;
            uint32_t afr[2][4];
            #pragma unroll
            for (int mi = 0; mi < 2; mi++)
                ldmx4(afr[mi], s2u(&sA[buf][wm * 32 + mi * 16 + lrow][k0 + lcol]));
            #pragma unroll
            for (int nb = 0; nb < 4; nb++) {
                uint32_t bm[4];
                ldmx4(bm, s2u(&sB[buf][wn * 64 + nb * 16 + lrow][k0 + lcol]));
                #pragma unroll
                for (int mi = 0; mi < 2; mi++) {
                    mma16816(acc[mi][2 * nb],     afr[mi], bm[0], bm[2]);
                    mma16816(acc[mi][2 * nb + 1], afr[mi], bm[1], bm[3]);
                }
            }
        }
        if (c + 1 < NCH) {
            __syncthreads();
            sts((c + 1) & 1);
            __syncthreads();
        }
    }

    // ---------------- epilogue: fragments -> g_qkv (bias + shift) ----------------
    const size_t PSZ = (size_t)B_ * H_ * N_ * HD_;
    float* qkvz = g_qkv + (size_t)z * PSZ;
    const int qrow = lane >> 2;
    const int qcol = (lane & 3) * 2;

    #pragma unroll
    for (int mi = 0; mi < 2; mi++) {
        #pragma unroll
        for (int hf = 0; hf < 2; hf++) {
            const int m  = m0 + wm * 32 + mi * 16 + qrow + hf * 8;
            const int b  = m >> 13;
            const int ns = m & (N_ - 1);
            #pragma unroll
            for (int ni = 0; ni < 8; ni++) {
                const int n = n0 + wn * 64 + ni * 8 + qcol;
                const int h = n >> 7;
                const int d = n & (HD_ - 1);
                const int nd = (h < HALF_) ? ns : ((ns - SHIFT_) & (N_ - 1));
                float* p = qkvz + (((size_t)b * H_ + h) * N_ + nd) * HD_ + d;
                p[0] = acc[mi][ni][hf * 2 + 0] + bias[n];
                p[1] = acc[mi][ni][hf * 2 + 1] + bias[n + 1];
            }
        }
    }
}

// ---------------------------------------------------------------------------
// Attention (proven in R3): one CTA per (b, h, group, 64-row q-tile)
// ---------------------------------------------------------------------------
#define QT_ 64
#define NQT 4
#define TSTR 68
#define SSTR 260

__global__ __launch_bounds__(256) void attn_kernel(float* __restrict__ y)
{
    extern __shared__ float smf[];
    float* Qt  = smf;
    float* KVt = smf + 128 * TSTR;
    float* Ss  = smf + 2 * 128 * TSTR;

    const int tid = threadIdx.x;
    const int tx = tid & 15;
    const int ty = tid >> 4;

    const int qt = blockIdx.x;
    const int g  = blockIdx.y;
    const int bh = blockIdx.z;
    const int b  = bh >> 4;
    const int h  = bh & 15;

    const size_t plane = ((size_t)b * H_ + h) * (size_t)N_ * HD_;
    const size_t PSZ   = (size_t)B_ * H_ * N_ * HD_;
    const float* qp = g_qkv + plane + (size_t)(g * GS_ + qt * QT_) * HD_;
    const float* kp = g_qkv + PSZ     + plane + (size_t)(g * GS_) * HD_;
    const float* vp = g_qkv + 2 * PSZ + plane + (size_t)(g * GS_) * HD_;

    #pragma unroll
    for (int i = 0; i < 8; i++) {
        int f  = tid + 256 * i;
        int r  = f >> 5;
        int d4 = f & 31;
        float4 v = *(const float4*)(qp + (size_t)r * HD_ + d4 * 4);
        Qt[(d4 * 4 + 0) * TSTR + r] = v.x;
        Qt[(d4 * 4 + 1) * TSTR + r] = v.y;
        Qt[(d4 * 4 + 2) * TSTR + r] = v.z;
        Qt[(d4 * 4 + 3) * TSTR + r] = v.w;
    }

    for (int kt = 0; kt <= qt; kt++) {
        __syncthreads();
        #pragma unroll
        for (int i = 0; i < 8; i++) {
            int f  = tid + 256 * i;
            int r  = f >> 5;
            int d4 = f & 31;
            float4 v = *(const float4*)(kp + ((size_t)kt * QT_ + r) * HD_ + d4 * 4);
            KVt[(d4 * 4 + 0) * TSTR + r] = v.x;
            KVt[(d4 * 4 + 1) * TSTR + r] = v.y;
            KVt[(d4 * 4 + 2) * TSTR + r] = v.z;
            KVt[(d4 * 4 + 3) * TSTR + r] = v.w;
        }
        __syncthreads();

        float s[4][4];
        #pragma unroll
        for (int i = 0; i < 4; i++)
            #pragma unroll
            for (int j = 0; j < 4; j++) s[i][j] = 0.f;

        #pragma unroll 4
        for (int d = 0; d < HD_; d++) {
            float4 qf = *(const float4*)&Qt[d * TSTR + ty * 4];
            float4 kf = *(const float4*)&KVt[d * TSTR + tx * 4];
            float rq[4] = {qf.x, qf.y, qf.z, qf.w};
            float rk[4] = {kf.x, kf.y, kf.z, kf.w};
            #pragma unroll
            for (int i = 0; i < 4; i++)
                #pragma unroll
                for (int j = 0; j < 4; j++)
                    s[i][j] = fmaf(rq[i], rk[j], s[i][j]);
        }
        #pragma unroll
        for (int i = 0; i < 4; i++) {
            int qi = qt * QT_ + ty * 4 + i;
            #pragma unroll
            for (int j = 0; j < 4; j++) {
                int ki = kt * QT_ + tx * 4 + j;
                Ss[(ty * 4 + i) * SSTR + ki] = (ki > qi) ? -1e9f : s[i][j] * SCALE_;
            }
        }
    }
    __syncthreads();

    {
        const int L = (qt + 1) * QT_;
        const int warp = tid >> 5, lane = tid & 31;
        for (int rr = 0; rr < 8; rr++) {
            float* row = Ss + (warp * 8 + rr) * SSTR;
            float m = -1e30f;
            for (int j = lane; j < L; j += 32) m = fmaxf(m, row[j]);
            #pragma unroll
            for (int o = 16; o; o >>= 1) m = fmaxf(m, __shfl_xor_sync(~0u, m, o));
            float sum = 0.f;
            for (int j = lane; j < L; j += 32) { float e = expf(row[j] - m); row[j] = e; sum += e; }
            #pragma unroll
            for (int o = 16; o; o >>= 1) sum += __shfl_xor_sync(~0u, sum, o);
            float inv = 1.f / sum;
            for (int j = lane; j < L; j += 32) row[j] *= inv;
        }
    }

    float acc[4][8];
    #pragma unroll
    for (int i = 0; i < 4; i++)
        #pragma unroll
        for (int j = 0; j < 8; j++) acc[i][j] = 0.f;

    for (int kt = 0; kt <= qt; kt++) {
        __syncthreads();
        #pragma unroll
        for (int i = 0; i < 8; i++) {
            int f  = tid + 256 * i;
            int r  = f >> 5;
            int d4 = f & 31;
            *(float4*)&KVt[r * 128 + d4 * 4] =
                *(const float4*)(vp + ((size_t)kt * QT_ + r) * HD_ + d4 * 4);
        }
        __syncthreads();

        #pragma unroll 2
        for (int kk = 0; kk < QT_; kk++) {
            const int kcol = kt * QT_ + kk;
            float p0 = Ss[(ty * 4 + 0) * SSTR + kcol];
            float p1 = Ss[(ty * 4 + 1) * SSTR + kcol];
            float p2 = Ss[(ty * 4 + 2) * SSTR + kcol];
            float p3 = Ss[(ty * 4 + 3) * SSTR + kcol];
            float4 v0 = *(const float4*)&KVt[kk * 128 + tx * 4];
            float4 v1 = *(const float4*)&KVt[kk * 128 + 64 + tx * 4];
            float rv[8] = {v0.x, v0.y, v0.z, v0.w, v1.x, v1.y, v1.z, v1.w};
            float rp[4] = {p0, p1, p2, p3};
            #pragma unroll
            for (int i = 0; i < 4; i++)
                #pragma unroll
                for (int j = 0; j < 8; j++)
                    acc[i][j] = fmaf(rp[i], rv[j], acc[i][j]);
        }
    }

    #pragma unroll
    for (int i = 0; i < 4; i++) {
        int np = g * GS_ + qt * QT_ + ty * 4 + i;
        int nf = (h < HALF_) ? np : ((np + SHIFT_) & (N_ - 1));
        float* orow = y + ((size_t)b * N_ + nf) * C_ + (size_t)h * HD_;
        *(float4*)(orow + tx * 4) =
            make_float4(acc[i][0], acc[i][1], acc[i][2], acc[i][3]);
        *(float4*)(orow + 64 + tx * 4) =
            make_float4(acc[i][4], acc[i][5], acc[i][6], acc[i][7]);
    }
}

// ---------------------------------------------------------------------------
extern "C" void kernel_launch(void* const* d_in, const int* in_sizes, int n_in,
                              void* d_out, int out_size)
{
    const float* x  = (const float*)d_in[0];
    const float* Wq = (const float*)d_in[1];
    const float* bq = (const float*)d_in[2];
    const float* Wk = (const float*)d_in[3];
    const float* bk = (const float*)d_in[4];
    const float* Wv = (const float*)d_in[5];
    const float* bv = (const float*)d_in[6];
    float* y = (float*)d_out;

    __nv_bfloat16 *Ag, *Bg;
    cudaGetSymbolAddress((void**)&Ag, g_A);
    cudaGetSymbolAddress((void**)&Bg, g_B);

    // hi/lo splits: A = [hi|lo|hi], B = [hi|hi|lo]
    split_kernel<<<MROWS * 2, 256>>>(x,  Ag, 2 * C_, C_);
    split_kernel<<<C_ * 2,    256>>>(Wq, Bg + (size_t)0 * C_ * K6, C_, 2 * C_);
    split_kernel<<<C_ * 2,    256>>>(Wk, Bg + (size_t)1 * C_ * K6, C_, 2 * C_);
    split_kernel<<<C_ * 2,    256>>>(Wv, Bg + (size_t)2 * C_ * K6, C_, 2 * C_);

    // HMMA projections (fused bias + shift scatter)
    gemm_kernel<<<dim3(C_ / 128, MROWS / 128, 3), 256>>>(bq, bk, bv);

    // attention
    const int att_smem = (2 * 128 * TSTR + 64 * SSTR) * (int)sizeof(float);
    cudaFuncSetAttribute(attn_kernel,
                         cudaFuncAttributeMaxDynamicSharedMemorySize, att_smem);
    attn_kernel<<<dim3(NQT, G_, B_ * H_), 256, att_smem>>>(y);
}

// round 6
// speedup vs baseline: 2.9444x; 1.1219x over previous
#include <cuda_runtime.h>
#include <cuda_bf16.h>
#include <math.h>
#include <stdint.h>

// ---------------------------------------------------------------------------
// Problem constants
// ---------------------------------------------------------------------------
#define B_    2
#define N_    8192
#define C_    2048
#define H_    16
#define HD_   128
#define GS_   256
#define G_    (N_/GS_)     // 32
#define HALF_ 8
#define SHIFT_ 128
#define SCALE_ 0.08838834764831843f   // 1/sqrt(128)
#define NEGF  -1e9f

#define MROWS (B_*N_)      // 16384
#define K6    (3*C_)       // 6144 augmented K: [hi|lo|hi] x [hi|hi|lo]

// scratch
__device__ __nv_bfloat16 g_A[(size_t)MROWS * K6];            // x_aug  [16384][6144]
__device__ __nv_bfloat16 g_B[(size_t)3 * C_ * K6];           // W_aug  [3][2048][6144]
__device__ __nv_bfloat16 g_hi[(size_t)3 * B_ * H_ * N_ * HD_];  // qkv hi (shifted)
__device__ __nv_bfloat16 g_lo[(size_t)3 * B_ * H_ * N_ * HD_];  // qkv lo (shifted)

// ---------------------------------------------------------------------------
// split: fp32 [rows][2048] -> bf16 [rows][6144]; hi at col 0 and hi2_off, lo at lo_off
// ---------------------------------------------------------------------------
__global__ __launch_bounds__(256) void split_kernel(
    const float* __restrict__ in, __nv_bfloat16* __restrict__ out,
    int hi2_off, int lo_off)
{
    size_t idx = (size_t)blockIdx.x * 256 + threadIdx.x;   // one float4 each
    float4 v = ((const float4*)in)[idx];
    size_t m  = idx >> 9;          // 512 float4 per row
    int    c  = (int)(idx & 511) * 4;

    __nv_bfloat16 h0 = __float2bfloat16(v.x);
    __nv_bfloat16 h1 = __float2bfloat16(v.y);
    __nv_bfloat16 h2 = __float2bfloat16(v.z);
    __nv_bfloat16 h3 = __float2bfloat16(v.w);
    __nv_bfloat16 l0 = __float2bfloat16(v.x - __bfloat162float(h0));
    __nv_bfloat16 l1 = __float2bfloat16(v.y - __bfloat162float(h1));
    __nv_bfloat16 l2 = __float2bfloat16(v.z - __bfloat162float(h2));
    __nv_bfloat16 l3 = __float2bfloat16(v.w - __bfloat162float(h3));

    __nv_bfloat162 hA(h0, h1), hB(h2, h3), lA(l0, l1), lB(l2, l3);
    __nv_bfloat16* rowp = out + m * K6;
    *(__nv_bfloat162*)(rowp + c)               = hA;
    *(__nv_bfloat162*)(rowp + c + 2)           = hB;
    *(__nv_bfloat162*)(rowp + hi2_off + c)     = hA;
    *(__nv_bfloat162*)(rowp + hi2_off + c + 2) = hB;
    *(__nv_bfloat162*)(rowp + lo_off + c)      = lA;
    *(__nv_bfloat162*)(rowp + lo_off + c + 2)  = lB;
}

// ---------------------------------------------------------------------------
// common MMA helpers (proven in R5)
// ---------------------------------------------------------------------------
__device__ __forceinline__ uint32_t s2u(const void* p) {
    uint32_t a;
    asm("{ .reg .u64 t; cvta.to.shared.u64 t, %1; cvt.u32.u64 %0, t; }"
        : "=r"(a) : "l"(p));
    return a;
}
__device__ __forceinline__ void ldmx4(uint32_t* r, uint32_t addr) {
    asm volatile("ldmatrix.sync.aligned.m8n8.x4.shared.b16 {%0,%1,%2,%3}, [%4];"
                 : "=r"(r[0]), "=r"(r[1]), "=r"(r[2]), "=r"(r[3]) : "r"(addr));
}
__device__ __forceinline__ void ldmx4t(uint32_t* r, uint32_t addr) {
    asm volatile("ldmatrix.sync.aligned.m8n8.x4.trans.shared.b16 {%0,%1,%2,%3}, [%4];"
                 : "=r"(r[0]), "=r"(r[1]), "=r"(r[2]), "=r"(r[3]) : "r"(addr));
}
__device__ __forceinline__ void mma16816(float* c, const uint32_t* a,
                                         uint32_t b0, uint32_t b1) {
    asm volatile(
        "mma.sync.aligned.m16n8k16.row.col.f32.bf16.bf16.f32 "
        "{%0,%1,%2,%3}, {%4,%5,%6,%7}, {%8,%9}, {%0,%1,%2,%3};"
        : "+f"(c[0]), "+f"(c[1]), "+f"(c[2]), "+f"(c[3])
        : "r"(a[0]), "r"(a[1]), "r"(a[2]), "r"(a[3]), "r"(b0), "r"(b1));
}

// ---------------------------------------------------------------------------
// HMMA GEMM (proven R5): D[m,n] = sum_k A[m,k]*B[n,k], K=6144, tile 128x128
// Epilogue now writes bf16 hi/lo q/k/v with fused bias + shift.
// ---------------------------------------------------------------------------
#define KC   32
#define LDA  40
#define NCH  (K6/KC)       // 192

__global__ __launch_bounds__(256, 2) void gemm_kernel(
    const float* __restrict__ bq, const float* __restrict__ bk,
    const float* __restrict__ bv)
{
    __shared__ __nv_bfloat16 sA[2][128][LDA];
    __shared__ __nv_bfloat16 sB[2][128][LDA];

    const int tid  = threadIdx.x;
    const int wid  = tid >> 5, lane = tid & 31;
    const int wm   = wid & 3;
    const int wn   = wid >> 2;

    const int n0 = blockIdx.x * 128;
    const int m0 = blockIdx.y * 128;
    const int z  = blockIdx.z;
    const __nv_bfloat16* __restrict__ Ap = g_A + (size_t)m0 * K6;
    const __nv_bfloat16* __restrict__ Bp = g_B + (size_t)z * C_ * K6 + (size_t)n0 * K6;
    const float* __restrict__ bias = (z == 0) ? bq : (z == 1) ? bk : bv;

    float acc[2][8][4];
    #pragma unroll
    for (int i = 0; i < 2; i++)
        #pragma unroll
        for (int j = 0; j < 8; j++)
            #pragma unroll
            for (int k = 0; k < 4; k++) acc[i][j][k] = 0.f;

    uint4 ra[2], rb[2];
    auto ldg = [&](int c) {
        const size_t k0 = (size_t)c * KC;
        #pragma unroll
        for (int i = 0; i < 2; i++) {
            int f = tid + 256 * i, row = f >> 2, c8 = (f & 3) * 8;
            ra[i] = *(const uint4*)(Ap + (size_t)row * K6 + k0 + c8);
            rb[i] = *(const uint4*)(Bp + (size_t)row * K6 + k0 + c8);
        }
    };
    auto sts = [&](int buf) {
        #pragma unroll
        for (int i = 0; i < 2; i++) {
            int f = tid + 256 * i, row = f >> 2, c8 = (f & 3) * 8;
            *(uint4*)&sA[buf][row][c8] = ra[i];
            *(uint4*)&sB[buf][row][c8] = rb[i];
        }
    };

    const int lrow = lane & 15;
    const int lcol = (lane >> 4) * 8;

    ldg(0); sts(0); __syncthreads();

    for (int c = 0; c < NCH; c++) {
        const int buf = c & 1;
        if (c + 1 < NCH) ldg(c + 1);

        #pragma unroll
        for (int ks = 0; ks < 2; ks++) {
            const int k0 = ks * 16;
            uint32_t afr[2][4];
            #pragma unroll
            for (int mi = 0; mi < 2; mi++)
                ldmx4(afr[mi], s2u(&sA[buf][wm * 32 + mi * 16 + lrow][k0 + lcol]));
            #pragma unroll
            for (int nb = 0; nb < 4; nb++) {
                uint32_t bm[4];
                ldmx4(bm, s2u(&sB[buf][wn * 64 + nb * 16 + lrow][k0 + lcol]));
                #pragma unroll
                for (int mi = 0; mi < 2; mi++) {
                    mma16816(acc[mi][2 * nb],     afr[mi], bm[0], bm[2]);
                    mma16816(acc[mi][2 * nb + 1], afr[mi], bm[1], bm[3]);
                }
            }
        }
        if (c + 1 < NCH) {
            __syncthreads();
            sts((c + 1) & 1);
            __syncthreads();
        }
    }

    // epilogue: fragments -> g_hi/g_lo (bias + shift), bf16 hi/lo
    const size_t PSZ = (size_t)B_ * H_ * N_ * HD_;
    __nv_bfloat16* hip = g_hi + (size_t)z * PSZ;
    __nv_bfloat16* lop = g_lo + (size_t)z * PSZ;
    const int qrow = lane >> 2;
    const int qcol = (lane & 3) * 2;

    #pragma unroll
    for (int mi = 0; mi < 2; mi++) {
        #pragma unroll
        for (int hf = 0; hf < 2; hf++) {
            const int m  = m0 + wm * 32 + mi * 16 + qrow + hf * 8;
            const int b  = m >> 13;
            const int ns = m & (N_ - 1);
            #pragma unroll
            for (int ni = 0; ni < 8; ni++) {
                const int n = n0 + wn * 64 + ni * 8 + qcol;
                const int hh = n >> 7;
                const int d  = n & (HD_ - 1);
                const int nd = (hh < HALF_) ? ns : ((ns - SHIFT_) & (N_ - 1));
                const size_t off = (((size_t)b * H_ + hh) * N_ + nd) * HD_ + d;
                float v0 = acc[mi][ni][hf * 2 + 0] + bias[n];
                float v1 = acc[mi][ni][hf * 2 + 1] + bias[n + 1];
                __nv_bfloat16 h0 = __float2bfloat16(v0);
                __nv_bfloat16 h1 = __float2bfloat16(v1);
                __nv_bfloat16 e0 = __float2bfloat16(v0 - __bfloat162float(h0));
                __nv_bfloat16 e1 = __float2bfloat16(v1 - __bfloat162float(h1));
                *(__nv_bfloat162*)(hip + off) = __nv_bfloat162(h0, h1);
                *(__nv_bfloat162*)(lop + off) = __nv_bfloat162(e0, e1);
            }
        }
    }
}

// ---------------------------------------------------------------------------
// HMMA attention: CTA per (qt, g, b*h). 256 threads = 8 warps.
//   phase A: S = Qaug @ Kaug^T (k=384) -> masked/scaled fp32 in smem
//   phase B: softmax (unnormalized), P split to bf16 hi/lo in smem
//   phase C: O = Ph Vh + Pl Vh + Ph Vl, scale by 1/rowsum, unshift-scatter to y
// smem union rows: 1072 B = [ S 256xfp32 | reused as Ph 256xbf16 + Pl 256xbf16 ]
// ---------------------------------------------------------------------------
#define OFF_RS  68608                 // 64*1072, fp32[64] row sums
#define OFF_Q   68864                 // bf16 [64][392]  (stride 784 B)
#define OFF_K   119040                // bf16 [64][392]
#define OFF_VH  119040                // reuse K region: bf16 [64][136] (stride 272 B)
#define OFF_VL  136448
#define AT_SMEM 169216

__global__ __launch_bounds__(256, 1) void attn_kernel(float* __restrict__ y)
{
    extern __shared__ char smc[];
    const int tid  = threadIdx.x;
    const int wid  = tid >> 5, lane = tid & 31;
    const int lrow = lane & 15, lcol = (lane >> 4) * 8;

    const int qt = blockIdx.x;               // 0..3
    const int g  = blockIdx.y;               // 0..31
    const int bh = blockIdx.z;
    const int b  = bh >> 4;
    const int h  = bh & 15;

    const size_t TOT   = (size_t)B_ * H_ * N_ * HD_;
    const size_t plane = ((size_t)b * H_ + h) * (size_t)N_ * HD_;
    const __nv_bfloat16* qh = g_hi + plane + (size_t)(g * GS_ + qt * 64) * HD_;
    const __nv_bfloat16* ql = g_lo + plane + (size_t)(g * GS_ + qt * 64) * HD_;
    const __nv_bfloat16* kh = g_hi + TOT     + plane + (size_t)(g * GS_) * HD_;
    const __nv_bfloat16* kl = g_lo + TOT     + plane + (size_t)(g * GS_) * HD_;
    const __nv_bfloat16* vh = g_hi + 2 * TOT + plane + (size_t)(g * GS_) * HD_;
    const __nv_bfloat16* vl = g_lo + 2 * TOT + plane + (size_t)(g * GS_) * HD_;

    // load Q: [Qh | Ql | Qh], 64 rows, stride 784 B
    #pragma unroll
    for (int i = 0; i < 4; i++) {
        int f = tid + 256 * i, r = f >> 4, c8 = (f & 15) * 8;
        uint4 hv = *(const uint4*)(qh + (size_t)r * HD_ + c8);
        uint4 lv = *(const uint4*)(ql + (size_t)r * HD_ + c8);
        char* rp = smc + OFF_Q + r * 784;
        *(uint4*)(rp + 2 * c8)         = hv;
        *(uint4*)(rp + 2 * (256 + c8)) = hv;
        *(uint4*)(rp + 2 * (128 + c8)) = lv;
    }

    // -------- phase A: scores --------
    const int wmA = wid & 3;      // 4 warps x 16 rows
    const int wnA = wid >> 2;     // 2 warps x 32 cols
    for (int kt = 0; kt <= qt; kt++) {
        __syncthreads();
        // load K chunk: [Kh | Kh | Kl]
        #pragma unroll
        for (int i = 0; i < 4; i++) {
            int f = tid + 256 * i, r = f >> 4, c8 = (f & 15) * 8;
            uint4 hv = *(const uint4*)(kh + (size_t)(kt * 64 + r) * HD_ + c8);
            uint4 lv = *(const uint4*)(kl + (size_t)(kt * 64 + r) * HD_ + c8);
            char* rp = smc + OFF_K + r * 784;
            *(uint4*)(rp + 2 * c8)         = hv;
            *(uint4*)(rp + 2 * (128 + c8)) = hv;
            *(uint4*)(rp + 2 * (256 + c8)) = lv;
        }
        __syncthreads();

        float accA[4][4];
        #pragma unroll
        for (int i = 0; i < 4; i++)
            #pragma unroll
            for (int j = 0; j < 4; j++) accA[i][j] = 0.f;

        #pragma unroll 4
        for (int ks = 0; ks < 24; ks++) {
            uint32_t afr[4];
            ldmx4(afr, s2u(smc + OFF_Q + (wmA * 16 + lrow) * 784 + 2 * (ks * 16 + lcol)));
            #pragma unroll
            for (int nb = 0; nb < 2; nb++) {
                uint32_t bm[4];
                ldmx4(bm, s2u(smc + OFF_K + (wnA * 32 + nb * 16 + lrow) * 784 + 2 * (ks * 16 + lcol)));
                mma16816(accA[nb * 2],     afr, bm[0], bm[2]);
                mma16816(accA[nb * 2 + 1], afr, bm[1], bm[3]);
            }
        }

        // mask + scale + store to S (fp32, union rows)
        const int qrow = wmA * 16 + (lane >> 2);
        const int qi0  = qt * 64 + qrow;
        const int qi1  = qi0 + 8;
        #pragma unroll
        for (int nt = 0; nt < 4; nt++) {
            int col = kt * 64 + wnA * 32 + nt * 8 + (lane & 3) * 2;
            float2 s0, s1;
            s0.x = (col     > qi0) ? NEGF : accA[nt][0] * SCALE_;
            s0.y = (col + 1 > qi0) ? NEGF : accA[nt][1] * SCALE_;
            s1.x = (col     > qi1) ? NEGF : accA[nt][2] * SCALE_;
            s1.y = (col + 1 > qi1) ? NEGF : accA[nt][3] * SCALE_;
            *(float2*)(smc + qrow * 1072 + 4 * col)       = s0;
            *(float2*)(smc + (qrow + 8) * 1072 + 4 * col) = s1;
        }
    }
    __syncthreads();

    // -------- phase B: softmax (unnormalized), write Ph/Pl bf16 --------
    {
        const int L  = (qt + 1) * 64;
        const int nv = L >> 5;               // 2,4,6,8
        for (int rr = 0; rr < 8; rr++) {
            const int r = wid * 8 + rr;
            float v[8];
            #pragma unroll
            for (int i = 0; i < 8; i++)
                if (i < nv) v[i] = *(const float*)(smc + r * 1072 + 4 * (lane + 32 * i));
            float m = -1e30f;
            #pragma unroll
            for (int i = 0; i < 8; i++) if (i < nv) m = fmaxf(m, v[i]);
            #pragma unroll
            for (int o = 16; o; o >>= 1) m = fmaxf(m, __shfl_xor_sync(~0u, m, o));
            float e[8];
            float sum = 0.f;
            #pragma unroll
            for (int i = 0; i < 8; i++)
                if (i < nv) { e[i] = __expf(v[i] - m); sum += e[i]; }
            __syncwarp();      // all S reads done before P overwrites the row
            #pragma unroll
            for (int i = 0; i < 8; i++)
                if (i < nv) {
                    __nv_bfloat16 ph = __float2bfloat16(e[i]);
                    __nv_bfloat16 pl = __float2bfloat16(e[i] - __bfloat162float(ph));
                    *(__nv_bfloat16*)(smc + r * 1072 + 2 * (lane + 32 * i))       = ph;
                    *(__nv_bfloat16*)(smc + r * 1072 + 512 + 2 * (lane + 32 * i)) = pl;
                }
            #pragma unroll
            for (int o = 16; o; o >>= 1) sum += __shfl_xor_sync(~0u, sum, o);
            if (lane == 0) *(float*)(smc + OFF_RS + 4 * r) = sum;
        }
    }
    __syncthreads();

    // -------- phase C: O = Ph Vh + Pl Vh + Ph Vl --------
    const int wmC = wid & 1;     // 2 warps x 32 rows
    const int wnC = wid >> 1;    // 4 warps x 32 d-cols
    float accC[2][4][4];
    #pragma unroll
    for (int a = 0; a < 2; a++)
        #pragma unroll
        for (int i = 0; i < 4; i++)
            #pragma unroll
            for (int j = 0; j < 4; j++) accC[a][i][j] = 0.f;

    for (int kt = 0; kt <= qt; kt++) {
        __syncthreads();
        #pragma unroll
        for (int i = 0; i < 4; i++) {
            int f = tid + 256 * i, r = f >> 4, c8 = (f & 15) * 8;
            *(uint4*)(smc + OFF_VH + r * 272 + 2 * c8) =
                *(const uint4*)(vh + (size_t)(kt * 64 + r) * HD_ + c8);
            *(uint4*)(smc + OFF_VL + r * 272 + 2 * c8) =
                *(const uint4*)(vl + (size_t)(kt * 64 + r) * HD_ + c8);
        }
        __syncthreads();

        #pragma unroll
        for (int pass = 0; pass < 3; pass++) {
            const int poff = (pass == 1) ? 512 : 0;        // Pl for pass 1
            const int voff = (pass == 2) ? OFF_VL : OFF_VH; // Vl for pass 2
            #pragma unroll
            for (int ks = 0; ks < 4; ks++) {
                uint32_t afr[2][4];
                #pragma unroll
                for (int mi = 0; mi < 2; mi++)
                    ldmx4(afr[mi], s2u(smc + (wmC * 32 + mi * 16 + lrow) * 1072 + poff
                                        + 2 * (kt * 64 + ks * 16 + lcol)));
                #pragma unroll
                for (int nb = 0; nb < 2; nb++) {
                    uint32_t bm[4];
                    ldmx4t(bm, s2u(smc + voff + (ks * 16 + lrow) * 272
                                    + 2 * (wnC * 32 + nb * 16 + lcol)));
                    #pragma unroll
                    for (int mi = 0; mi < 2; mi++) {
                        mma16816(accC[mi][nb * 2],     afr[mi], bm[0], bm[1]);
                        mma16816(accC[mi][nb * 2 + 1], afr[mi], bm[2], bm[3]);
                    }
                }
            }
        }
    }

    // epilogue: scale by 1/rowsum, unshift + head-interleave into y
    #pragma unroll
    for (int mi = 0; mi < 2; mi++) {
        const int row  = wmC * 32 + mi * 16 + (lane >> 2);
        const float i0 = 1.f / *(const float*)(smc + OFF_RS + 4 * row);
        const float i1 = 1.f / *(const float*)(smc + OFF_RS + 4 * (row + 8));
        const int np0 = g * GS_ + qt * 64 + row;
        const int np1 = np0 + 8;
        const int nf0 = (h < HALF_) ? np0 : ((np0 + SHIFT_) & (N_ - 1));
        const int nf1 = (h < HALF_) ? np1 : ((np1 + SHIFT_) & (N_ - 1));
        float* y0 = y + ((size_t)b * N_ + nf0) * C_ + h * HD_;
        float* y1 = y + ((size_t)b * N_ + nf1) * C_ + h * HD_;
        #pragma unroll
        for (int nt = 0; nt < 4; nt++) {
            const int d = wnC * 32 + nt * 8 + (lane & 3) * 2;
            *(float2*)(y0 + d) = make_float2(accC[mi][nt][0] * i0, accC[mi][nt][1] * i0);
            *(float2*)(y1 + d) = make_float2(accC[mi][nt][2] * i1, accC[mi][nt][3] * i1);
        }
    }
}

// ---------------------------------------------------------------------------
extern "C" void kernel_launch(void* const* d_in, const int* in_sizes, int n_in,
                              void* d_out, int out_size)
{
    const float* x  = (const float*)d_in[0];
    const float* Wq = (const float*)d_in[1];
    const float* bq = (const float*)d_in[2];
    const float* Wk = (const float*)d_in[3];
    const float* bk = (const float*)d_in[4];
    const float* Wv = (const float*)d_in[5];
    const float* bv = (const float*)d_in[6];
    float* y = (float*)d_out;

    __nv_bfloat16 *Ag, *Bg;
    cudaGetSymbolAddress((void**)&Ag, g_A);
    cudaGetSymbolAddress((void**)&Bg, g_B);

    // hi/lo splits: A = [hi|lo|hi], B = [hi|hi|lo]
    split_kernel<<<MROWS * 2, 256>>>(x,  Ag, 2 * C_, C_);
    split_kernel<<<C_ * 2,    256>>>(Wq, Bg + (size_t)0 * C_ * K6, C_, 2 * C_);
    split_kernel<<<C_ * 2,    256>>>(Wk, Bg + (size_t)1 * C_ * K6, C_, 2 * C_);
    split_kernel<<<C_ * 2,    256>>>(Wv, Bg + (size_t)2 * C_ * K6, C_, 2 * C_);

    // HMMA projections (fused bias + shift scatter, bf16 hi/lo output)
    gemm_kernel<<<dim3(C_ / 128, MROWS / 128, 3), 256>>>(bq, bk, bv);

    // HMMA attention
    cudaFuncSetAttribute(attn_kernel,
                         cudaFuncAttributeMaxDynamicSharedMemorySize, AT_SMEM);
    attn_kernel<<<dim3(4, G_, B_ * H_), 256, AT_SMEM>>>(y);
}